// round 3
// baseline (speedup 1.0000x reference)
#include <cuda_runtime.h>
#include <math.h>

#define N 96
#define NN (N*N)            // 9216
#define LATENT 256
#define OUT_DIM 4656
#define ITERS 50
#define NBLK_E 48           // each block handles 2 'a' values
#define CHUNK 96            // 9216 / 96 blocks

// ---------------- static device scratch (no allocations allowed) ----------------
__device__ float g_part_mu[96 * LATENT];
__device__ float g_part_ls[96 * LATENT];
__device__ float g_hidden[LATENT];
__device__ float g_kl;
__device__ float g_out[OUT_DIM];
__device__ float g_bce[64];
__device__ float g_sd[N], g_sdr[N], g_sfe[N], g_sfr[N];
__device__ float g_A[NN];        // A'[i*N+j]
__device__ float g_Bm[NN];       // B'[a*N+b]
__device__ float g_SdT[NN];      // Sd transposed: [a*N+i]
__device__ float g_u[2][NN];     // x transposed: u[b*N + j] = x[j][b]
__device__ float g_sumsq[ITERS + 1];
__device__ unsigned int g_bar_count;
__device__ volatile unsigned int g_bar_release;

__device__ __forceinline__ int trioff(int i) { return i * (193 - i) / 2; }

// ---------------- Kernel A: split-K encoder matvec partials ----------------
__global__ void kA(const float* __restrict__ h,
                   const float* __restrict__ We11,
                   const float* __restrict__ We12) {
    __shared__ float sh[CHUNK];
    int b = blockIdx.x, t = threadIdx.x;
    if (t < CHUNK) sh[t] = h[b * CHUNK + t];
    __syncthreads();
    float smu = 0.f, sls = 0.f;
    long base = (long)b * CHUNK * LATENT + t;
#pragma unroll 4
    for (int k = 0; k < CHUNK; k++) {
        float hv = sh[k];
        smu = fmaf(hv, We11[base + (long)k * LATENT], smu);
        sls = fmaf(hv, We12[base + (long)k * LATENT], sls);
    }
    g_part_mu[b * LATENT + t] = smu;
    g_part_ls[b * LATENT + t] = sls;
}

// ---------------- Kernel B: reduce, reparam, KL, hidden layer ----------------
__global__ void kB(const float* __restrict__ eps,
                   const float* __restrict__ be11,
                   const float* __restrict__ be12,
                   const float* __restrict__ Wd1,
                   const float* __restrict__ bd1) {
    int t = threadIdx.x;
    float mu = be11[t], ls = be12[t];
#pragma unroll 4
    for (int b = 0; b < 96; b++) {
        mu += g_part_mu[b * LATENT + t];
        ls += g_part_ls[b * LATENT + t];
    }
    float z = fmaf(eps[t], expf(0.5f * ls), mu);
    float klp = 1.0f + ls - mu * mu - expf(ls);

    __shared__ float sz[LATENT];
    __shared__ float sred[8];
    sz[t] = z;
#pragma unroll
    for (int off = 16; off; off >>= 1) klp += __shfl_xor_sync(0xffffffffu, klp, off);
    if ((t & 31) == 0) sred[t >> 5] = klp;
    __syncthreads();
    if (t == 0) {
        float s = 0.f;
#pragma unroll
        for (int w = 0; w < 8; w++) s += sred[w];
        g_kl = -0.5f * s / (float)NN;
    }
    float acc = bd1[t];
#pragma unroll 8
    for (int l = 0; l < LATENT; l++) acc = fmaf(sz[l], Wd1[l * LATENT + t], acc);
    g_hidden[t] = fmaxf(acc, 0.f);
}

// ---------------- Kernel C: output layer, sigmoid, BCE partials ----------------
__global__ void kC(const float* __restrict__ Wd2,
                   const float* __restrict__ bd2,
                   const float* __restrict__ adj) {
    __shared__ float sH[LATENT];
    __shared__ float sred[4];
    int t = threadIdx.x;
    sH[t] = g_hidden[t];
    sH[t + 128] = g_hidden[t + 128];
    __syncthreads();
    int o = blockIdx.x * 128 + t;
    float term = 0.f;
    if (o < OUT_DIM) {
        float y = bd2[o];
#pragma unroll 8
        for (int l = 0; l < LATENT; l++) y = fmaf(sH[l], Wd2[l * OUT_DIM + o], y);
        float ov = 1.f / (1.f + expf(-y));
        g_out[o] = ov;
        // invert triu index: o -> (i,j), i<=j
        int i = (int)((193.0f - sqrtf(37249.0f - 8.0f * (float)o)) * 0.5f);
        if (i < 0) i = 0;
        if (i > 95) i = 95;
        while (i < 95 && trioff(i + 1) <= o) i++;
        while (i > 0 && trioff(i) > o) i--;
        int j = o - trioff(i) + i;
        float inp = adj[i * N + j];
        float li = fmaxf(logf(inp), -100.f);
        float l1 = fmaxf(log1pf(-inp), -100.f);
        term = fmaf(ov, li, (1.f - ov) * l1);
    }
#pragma unroll
    for (int off = 16; off; off >>= 1) term += __shfl_xor_sync(0xffffffffu, term, off);
    if ((t & 31) == 0) sred[t >> 5] = term;
    __syncthreads();
    if (t == 0) g_bce[blockIdx.x] = sred[0] + sred[1] + sred[2] + sred[3];
}

// ---------------- Kernel D1: per-node stats, loss finalize, barrier init ------
__global__ void kD1(const float* __restrict__ adj, float* __restrict__ d_out,
                    int write_loss) {
    int t = threadIdx.x;   // 96 threads
    if (t < N) {
        float s = 0.f;
#pragma unroll 4
        for (int j = 0; j < N; j++) s += adj[t * N + j];
        g_sfe[t] = s;
        g_sd[t] = adj[t * N + t];
        g_sdr[t] = g_out[trioff(t)];
        float sr = 0.f;
        for (int b = 0; b < N; b++) {
            int lo = min(t, b), hi = max(t, b);
            sr += g_out[trioff(lo) + hi - lo];
        }
        g_sfr[t] = sr;
    }
    if (t >= 1 && t <= ITERS) g_sumsq[t] = 0.f;
    if (t == 0) {
        g_sumsq[0] = 1.0f;   // ||x0||^2 = 9216 * (1/96)^2 = 1
        g_bar_count = 0u;
        g_bar_release = 0u;
        float s = 0.f;
        for (int b = 0; b < 37; b++) s += g_bce[b];
        if (write_loss) d_out[0] = -s / (float)OUT_DIM + g_kl;
    }
}

// ---------------- Kernel D2: fill A', B', Sd, init MPM state (36 blocks) ------
__global__ void kD2(const float* __restrict__ adj) {
    __shared__ float sd[N], sdr[N], sfe[N], sfr[N];
    int t = threadIdx.x;
    if (t < N) { sd[t] = g_sd[t]; sdr[t] = g_sdr[t]; sfe[t] = g_sfe[t]; sfr[t] = g_sfr[t]; }
    __syncthreads();
    int idx = blockIdx.x * 256 + t;
    int i = idx / N, j = idx - i * N;
    g_A[idx] = (i != j) ? adj[idx] * sd[i] * sd[j] : 0.f;
    int lo = min(i, j), hi = max(i, j);
    float rec = g_out[trioff(lo) + hi - lo];
    g_Bm[idx] = (i != j) ? rec * sdr[i] * sdr[j] : 0.f;
    // idx = a*N + i2 for SdT
    g_SdT[idx] = sd[j] * sdr[i] / (fabsf(sfe[j] - sfr[i]) + 1.0f);
    g_u[0][idx] = 1.0f / 96.0f;
}

// ---------------- Kernel E: persistent MPM, 2 'a' rows per block --------------
__global__ void __launch_bounds__(192) kE(float* __restrict__ d_out, int base) {
    __shared__ float sM0[N], sM1[N];
    __shared__ float sred[6];
    int t = threadIdx.x;            // 192 threads, all active
    int lane = t & 31;
    int a0 = blockIdx.x * 2, a1 = a0 + 1;
    int row = t >> 1;               // j in M-phase, i in update phase
    int half = t & 1;
    int b0 = half * 48;

    float rB0[48], rB1[48], rA[48];
#pragma unroll
    for (int q = 0; q < 48; q++) {
        rB0[q] = g_Bm[a0 * N + b0 + q];
        rB1[q] = g_Bm[a1 * N + b0 + q];
        rA[q]  = g_A [row * N + b0 + q];
    }
    float rSd0 = g_SdT[a0 * N + row];
    float rSd1 = g_SdT[a1 * N + row];

    for (int k = 0; k < ITERS; k++) {
        const float* ur = g_u[k & 1];
        float* uw = g_u[(k + 1) & 1];
        // issue long-latency independent loads first (overlap with M-phase)
        float rinv  = rsqrtf(__ldcg(&g_sumsq[k]));
        float uold0 = __ldcg(&ur[a0 * N + row]);
        float uold1 = __ldcg(&ur[a1 * N + row]);

        // ---- M_a[j] = max_b B'[a,b] * x[j,b]; each u value feeds both a's ----
        float m00 = 0.f, m01 = 0.f, m10 = 0.f, m11 = 0.f;
#pragma unroll
        for (int q = 0; q < 48; q += 2) {
            float u0 = __ldcg(&ur[(b0 + q)     * N + row]);
            float u1 = __ldcg(&ur[(b0 + q + 1) * N + row]);
            m00 = fmaxf(m00, rB0[q]     * u0);
            m10 = fmaxf(m10, rB1[q]     * u0);
            m01 = fmaxf(m01, rB0[q + 1] * u1);
            m11 = fmaxf(m11, rB1[q + 1] * u1);
        }
        float M0 = fmaxf(m00, m01), M1 = fmaxf(m10, m11);
        M0 = fmaxf(M0, __shfl_xor_sync(0xffffffffu, M0, 1));
        M1 = fmaxf(M1, __shfl_xor_sync(0xffffffffu, M1, 1));
        if (!half) { sM0[row] = M0; sM1[row] = M1; }
        __syncthreads();

        // ---- x_new[i,a] = rinv * (x[i,a]*Sd[a,i] + sum_j A'[i,j] M_a[j]) ----
        float c00 = 0.f, c01 = 0.f, c10 = 0.f, c11 = 0.f;
#pragma unroll
        for (int q = 0; q < 48; q += 2) {
            float s0a = sM0[b0 + q], s0b = sM0[b0 + q + 1];
            float s1a = sM1[b0 + q], s1b = sM1[b0 + q + 1];
            c00 = fmaf(rA[q],     s0a, c00);
            c01 = fmaf(rA[q + 1], s0b, c01);
            c10 = fmaf(rA[q],     s1a, c10);
            c11 = fmaf(rA[q + 1], s1b, c11);
        }
        float acc0 = c00 + c01, acc1 = c10 + c11;
        acc0 += __shfl_xor_sync(0xffffffffu, acc0, 1);
        acc1 += __shfl_xor_sync(0xffffffffu, acc1, 1);
        float sq = 0.f;
        if (!half) {
            float v0 = rinv * fmaf(uold0, rSd0, acc0);
            float v1 = rinv * fmaf(uold1, rSd1, acc1);
            __stcg(&uw[a0 * N + row], v0);
            __stcg(&uw[a1 * N + row], v1);
            sq = fmaf(v0, v0, v1 * v1);
        }
#pragma unroll
        for (int off = 16; off; off >>= 1) sq += __shfl_xor_sync(0xffffffffu, sq, off);
        if (lane == 0) sred[t >> 5] = sq;
        __syncthreads();

        // ---- global barrier (48 blocks, all co-resident) ----
        if (t == 0) {
            float s = ((sred[0] + sred[1]) + (sred[2] + sred[3])) + (sred[4] + sred[5]);
            atomicAdd(&g_sumsq[k + 1], s);
            __threadfence();
            unsigned tgt = (unsigned)(k + 1) * (unsigned)NBLK_E;
            unsigned prev = atomicAdd(&g_bar_count, 1u);
            if (prev + 1u == tgt) {
                g_bar_release = (unsigned)(k + 1);
            } else {
                while (g_bar_release < (unsigned)(k + 1)) {}
                __threadfence();
            }
        }
        __syncthreads();
    }

    float rinvF = rsqrtf(__ldcg(&g_sumsq[ITERS]));
    const float* uf = g_u[ITERS & 1];   // ITERS even -> buffer 0
    if (t < N) {
        d_out[base + t * N + a0] = __ldcg(&uf[a0 * N + t]) * rinvF;
    } else {
        int i = t - N;
        d_out[base + i * N + a1] = __ldcg(&uf[a1 * N + i]) * rinvF;
    }
}

// ---------------- launch ----------------
extern "C" void kernel_launch(void* const* d_in, const int* in_sizes, int n_in,
                              void* d_out, int out_size) {
    const float* feats = (const float*)d_in[0];
    const float* adj   = (const float*)d_in[1];
    const float* eps   = (const float*)d_in[2];
    const float* We11  = (const float*)d_in[3];
    const float* be11  = (const float*)d_in[4];
    const float* We12  = (const float*)d_in[5];
    const float* be12  = (const float*)d_in[6];
    const float* Wd1   = (const float*)d_in[7];
    const float* bd1   = (const float*)d_in[8];
    const float* Wd2   = (const float*)d_in[9];
    const float* bd2   = (const float*)d_in[10];
    float* out = (float*)d_out;

    int has_loss = (out_size > NN) ? 1 : 0;
    int base = has_loss ? 1 : 0;

    kA<<<96, 256>>>(feats, We11, We12);
    kB<<<1, 256>>>(eps, be11, be12, Wd1, bd1);
    kC<<<37, 128>>>(Wd2, bd2, adj);
    kD1<<<1, 96>>>(adj, out, has_loss);
    kD2<<<36, 256>>>(adj);
    kE<<<NBLK_E, 192>>>(out, base);
}

// round 4
// speedup vs baseline: 1.1870x; 1.1870x over previous
#include <cuda_runtime.h>
#include <math.h>

#define N 96
#define NN (N*N)            // 9216
#define LATENT 256
#define OUT_DIM 4656
#define ITERS 50
#define NBLK_E 96
#define CHUNK 96            // 9216 / 96 blocks for kA

// ---------------- static device scratch (no allocations allowed) ----------------
__device__ float g_part_mu[96 * LATENT];
__device__ float g_part_ls[96 * LATENT];
__device__ float g_hidden[LATENT];
__device__ float g_kl;
__device__ float g_out[OUT_DIM];
__device__ float g_bce[64];
__device__ float g_sd[N], g_sdr[N], g_sfe[N], g_sfr[N];
__device__ float g_u[2][NN];     // x transposed: u[b*N + j] = x[j][b]
__device__ float g_sumsq[ITERS + 1];
__device__ float g_psq[NBLK_E];          // per-block norm partials
__device__ unsigned int g_arrive[NBLK_E];// per-block epoch flags
__device__ unsigned int g_release;       // leader-published epoch

__device__ __forceinline__ int trioff(int i) { return i * (193 - i) / 2; }

// ---------------- Kernel A: split-K encoder matvec partials ----------------
__global__ void kA(const float* __restrict__ h,
                   const float* __restrict__ We11,
                   const float* __restrict__ We12) {
    __shared__ float sh[CHUNK];
    int b = blockIdx.x, t = threadIdx.x;
    if (t < CHUNK) sh[t] = h[b * CHUNK + t];
    __syncthreads();
    float smu = 0.f, sls = 0.f;
    long base = (long)b * CHUNK * LATENT + t;
#pragma unroll 4
    for (int k = 0; k < CHUNK; k++) {
        float hv = sh[k];
        smu = fmaf(hv, We11[base + (long)k * LATENT], smu);
        sls = fmaf(hv, We12[base + (long)k * LATENT], sls);
    }
    g_part_mu[b * LATENT + t] = smu;
    g_part_ls[b * LATENT + t] = sls;
}

// ---------------- Kernel B: reduce, reparam, KL, hidden layer ----------------
__global__ void kB(const float* __restrict__ eps,
                   const float* __restrict__ be11,
                   const float* __restrict__ be12,
                   const float* __restrict__ Wd1,
                   const float* __restrict__ bd1) {
    int t = threadIdx.x;
    float mu = be11[t], ls = be12[t];
#pragma unroll 4
    for (int b = 0; b < 96; b++) {
        mu += g_part_mu[b * LATENT + t];
        ls += g_part_ls[b * LATENT + t];
    }
    float z = fmaf(eps[t], expf(0.5f * ls), mu);
    float klp = 1.0f + ls - mu * mu - expf(ls);

    __shared__ float sz[LATENT];
    __shared__ float sred[8];
    sz[t] = z;
#pragma unroll
    for (int off = 16; off; off >>= 1) klp += __shfl_xor_sync(0xffffffffu, klp, off);
    if ((t & 31) == 0) sred[t >> 5] = klp;
    __syncthreads();
    if (t == 0) {
        float s = 0.f;
#pragma unroll
        for (int w = 0; w < 8; w++) s += sred[w];
        g_kl = -0.5f * s / (float)NN;
    }
    float acc = bd1[t];
#pragma unroll 8
    for (int l = 0; l < LATENT; l++) acc = fmaf(sz[l], Wd1[l * LATENT + t], acc);
    g_hidden[t] = fmaxf(acc, 0.f);
}

// ---------------- Kernel C: output layer, sigmoid, BCE partials ----------------
__global__ void kC(const float* __restrict__ Wd2,
                   const float* __restrict__ bd2,
                   const float* __restrict__ adj) {
    __shared__ float sH[LATENT];
    __shared__ float sred[4];
    int t = threadIdx.x;
    sH[t] = g_hidden[t];
    sH[t + 128] = g_hidden[t + 128];
    __syncthreads();
    int o = blockIdx.x * 128 + t;
    float term = 0.f;
    if (o < OUT_DIM) {
        float y = bd2[o];
#pragma unroll 8
        for (int l = 0; l < LATENT; l++) y = fmaf(sH[l], Wd2[l * OUT_DIM + o], y);
        float ov = 1.f / (1.f + expf(-y));
        g_out[o] = ov;
        // invert triu index: o -> (i,j), i<=j
        int i = (int)((193.0f - sqrtf(37249.0f - 8.0f * (float)o)) * 0.5f);
        if (i < 0) i = 0;
        if (i > 95) i = 95;
        while (i < 95 && trioff(i + 1) <= o) i++;
        while (i > 0 && trioff(i) > o) i--;
        int j = o - trioff(i) + i;
        float inp = adj[i * N + j];
        float li = fmaxf(logf(inp), -100.f);
        float l1 = fmaxf(log1pf(-inp), -100.f);
        term = fmaf(ov, li, (1.f - ov) * l1);
    }
#pragma unroll
    for (int off = 16; off; off >>= 1) term += __shfl_xor_sync(0xffffffffu, term, off);
    if ((t & 31) == 0) sred[t >> 5] = term;
    __syncthreads();
    if (t == 0) g_bce[blockIdx.x] = sred[0] + sred[1] + sred[2] + sred[3];
}

// ---------------- Kernel D1: stats, loss finalize, MPM init (1024 threads) ----
__global__ void kD1(const float* __restrict__ adj, float* __restrict__ d_out,
                    int write_loss) {
    int t = threadIdx.x;
    int node = t >> 3, sub = t & 7;          // 8 lanes per node
    if (node < N) {
        float se = 0.f, sr = 0.f;
#pragma unroll
        for (int i = 0; i < 12; i++) {
            int b = sub * 12 + i;
            se += adj[node * N + b];
            int lo = min(node, b), hi = max(node, b);
            sr += g_out[trioff(lo) + hi - lo];
        }
        se += __shfl_xor_sync(0xffffffffu, se, 1);
        se += __shfl_xor_sync(0xffffffffu, se, 2);
        se += __shfl_xor_sync(0xffffffffu, se, 4);
        sr += __shfl_xor_sync(0xffffffffu, sr, 1);
        sr += __shfl_xor_sync(0xffffffffu, sr, 2);
        sr += __shfl_xor_sync(0xffffffffu, sr, 4);
        if (sub == 0) {
            g_sfe[node] = se;
            g_sfr[node] = sr;
            g_sd[node]  = adj[node * N + node];
            g_sdr[node] = g_out[trioff(node)];
        }
    }
    // init MPM state
    for (int i = t; i < NN; i += 1024) g_u[0][i] = 1.0f / 96.0f;
    if (t < NBLK_E) g_arrive[t] = 0u;
    if (t == 0) {
        g_release = 0u;
        g_sumsq[0] = 1.0f;   // ||x0||^2 = 9216*(1/96)^2 = 1
        float s = 0.f;
        for (int b = 0; b < 37; b++) s += g_bce[b];
        if (write_loss) d_out[0] = -s / (float)OUT_DIM + g_kl;
    }
}

// ---------------- Kernel E: persistent MPM, flag-array barrier ----------------
__global__ void __launch_bounds__(384) kE(const float* __restrict__ adj,
                                          float* __restrict__ d_out, int base) {
    __shared__ float ssd[N], ssdr[N];
    __shared__ float sMp[4][N];    // per-quarter max partials
    __shared__ float sCp[4][N];    // per-quarter sum partials
    __shared__ float sM[N];
    __shared__ float sred[3], sred2[3];
    __shared__ float sRinv;

    int t = threadIdx.x, lane = t & 31, warp = t >> 5;   // 12 warps
    int rowg = warp % 3, quarter = warp / 3;
    int row = rowg * 32 + lane;
    int b0 = quarter * 24;
    int a = blockIdx.x;

    if (t < N) { ssd[t] = g_sd[t]; ssdr[t] = g_sdr[t]; }
    if (t == 0) sRinv = 1.0f;
    __syncthreads();

    // ---- prologue: build rB (B' row a), rA (A' row 'row'), rSd in registers ----
    float rB[24], rA[24];
    float sdr_a = ssdr[a];
#pragma unroll
    for (int q = 0; q < 24; q++) {
        int b = b0 + q;
        rA[q] = (row != b) ? adj[row * N + b] * ssd[row] * ssd[b] : 0.f;
        int lo = min(a, b), hi = max(a, b);
        float rec = g_out[trioff(lo) + hi - lo];
        rB[q] = (a != b) ? rec * sdr_a * ssdr[b] : 0.f;
    }
    float rSd = 0.f;
    if (quarter == 0)
        rSd = ssd[row] * sdr_a / (fabsf(g_sfe[row] - g_sfr[a]) + 1.0f);

    float vlast = 0.f;

    for (int k = 0; k < ITERS; k++) {
        const float* ur = g_u[k & 1];
        float* uw = g_u[(k + 1) & 1];
        float uold = (quarter == 0) ? __ldcg(&ur[a * N + row]) : 0.f;

        // ---- M partial: max over this quarter's 24 b values (coalesced loads) ----
        float m0 = 0.f, m1 = 0.f, m2 = 0.f, m3 = 0.f;
#pragma unroll
        for (int q = 0; q < 24; q += 4) {
            m0 = fmaxf(m0, rB[q]     * __ldcg(&ur[(b0 + q)     * N + row]));
            m1 = fmaxf(m1, rB[q + 1] * __ldcg(&ur[(b0 + q + 1) * N + row]));
            m2 = fmaxf(m2, rB[q + 2] * __ldcg(&ur[(b0 + q + 2) * N + row]));
            m3 = fmaxf(m3, rB[q + 3] * __ldcg(&ur[(b0 + q + 3) * N + row]));
        }
        sMp[quarter][row] = fmaxf(fmaxf(m0, m1), fmaxf(m2, m3));
        __syncthreads();

        // ---- combine quarters: M[j] ----
        if (t < N) sM[t] = fmaxf(fmaxf(sMp[0][t], sMp[1][t]),
                                 fmaxf(sMp[2][t], sMp[3][t]));
        __syncthreads();

        // ---- update partial: sum over this quarter's 24 j values ----
        float c0 = 0.f, c1 = 0.f, c2 = 0.f, c3 = 0.f;
#pragma unroll
        for (int q = 0; q < 24; q += 4) {
            c0 = fmaf(rA[q],     sM[b0 + q],     c0);
            c1 = fmaf(rA[q + 1], sM[b0 + q + 1], c1);
            c2 = fmaf(rA[q + 2], sM[b0 + q + 2], c2);
            c3 = fmaf(rA[q + 3], sM[b0 + q + 3], c3);
        }
        sCp[quarter][row] = (c0 + c1) + (c2 + c3);
        __syncthreads();

        // ---- finalize column a, store, norm partial ----
        if (quarter == 0) {
            float acc = (sCp[0][row] + sCp[1][row]) + (sCp[2][row] + sCp[3][row]);
            float v = sRinv * fmaf(uold, rSd, acc);
            __stcg(&uw[a * N + row], v);
            vlast = v;
            float sq = v * v;
#pragma unroll
            for (int off = 16; off; off >>= 1)
                sq += __shfl_xor_sync(0xffffffffu, sq, off);
            if (lane == 0) sred[rowg] = sq;
        }
        __syncthreads();

        // ---- arrival: one plain store per block (no same-address atomics) ----
        if (t == 0) {
            __stcg(&g_psq[a], sred[0] + sred[1] + sred[2]);
            __threadfence();
            *((volatile unsigned int*)&g_arrive[a]) = (unsigned)(k + 1);
        }

        // ---- leader block: poll all flags in parallel, reduce, release ----
        if (a == 0) {
            if (t < NBLK_E) {
                volatile unsigned int* fl = (volatile unsigned int*)&g_arrive[t];
                while (*fl < (unsigned)(k + 1)) {}
            }
            __syncthreads();
            __threadfence();
            float p = (t < NBLK_E) ? __ldcg(&g_psq[t]) : 0.f;
#pragma unroll
            for (int off = 16; off; off >>= 1)
                p += __shfl_xor_sync(0xffffffffu, p, off);
            if (lane == 0 && warp < 3) sred2[warp] = p;
            __syncthreads();
            if (t == 0) {
                __stcg(&g_sumsq[k + 1], sred2[0] + sred2[1] + sred2[2]);
                __threadfence();
                *((volatile unsigned int*)&g_release) = (unsigned)(k + 1);
            }
        }

        // ---- all blocks: wait for release, refresh rinv ----
        if (t == 0) {
            volatile unsigned int* rl = (volatile unsigned int*)&g_release;
            while (*rl < (unsigned)(k + 1)) {}
            __threadfence();
            sRinv = rsqrtf(__ldcg(&g_sumsq[k + 1]));
        }
        __syncthreads();
    }

    // ---- output: final column from registers, exact final normalization ----
    if (quarter == 0) {
        float rinvF = rsqrtf(__ldcg(&g_sumsq[ITERS]));
        d_out[base + row * N + a] = vlast * rinvF;
    }
}

// ---------------- launch ----------------
extern "C" void kernel_launch(void* const* d_in, const int* in_sizes, int n_in,
                              void* d_out, int out_size) {
    const float* feats = (const float*)d_in[0];
    const float* adj   = (const float*)d_in[1];
    const float* eps   = (const float*)d_in[2];
    const float* We11  = (const float*)d_in[3];
    const float* be11  = (const float*)d_in[4];
    const float* We12  = (const float*)d_in[5];
    const float* be12  = (const float*)d_in[6];
    const float* Wd1   = (const float*)d_in[7];
    const float* bd1   = (const float*)d_in[8];
    const float* Wd2   = (const float*)d_in[9];
    const float* bd2   = (const float*)d_in[10];
    float* out = (float*)d_out;

    int has_loss = (out_size > NN) ? 1 : 0;
    int base = has_loss ? 1 : 0;

    kA<<<96, 256>>>(feats, We11, We12);
    kB<<<1, 256>>>(eps, be11, be12, Wd1, bd1);
    kC<<<37, 128>>>(Wd2, bd2, adj);
    kD1<<<1, 1024>>>(adj, out, has_loss);
    kE<<<NBLK_E, 384>>>(adj, out, base);
}